// round 2
// baseline (speedup 1.0000x reference)
#include <cuda_runtime.h>

// Vector_Quantizer eval forward:
//   x: [32,64,64,64] f32, embedding: [1024,64] f32
//   out (float32, 8519681): [loss(1) | quantized(8388608, BCHW) | indices(131072)]
//
// Strategy: distance argmin is an fp32 "GEMM" (131072x1024x64 MAC) -> fp32 FMA bound.
// Use packed fma.rn.f32x2 (2x FFMA throughput on sm_103a), packing lanes along C.
// 128-pixel blocks, 128-code smem tiles, 8x8 register tile per thread.

#define KCODES 1024
#define CDIM 64
#define NPIX 131072
#define PIX_PER_BLK 128
#define CODE_TILE 128
#define NTILES (KCODES / CODE_TILE)
#define PAD 68          // floats per smem row: 16B-aligned, avoids 0 mod 32 bank stride
#define QELEMS 8388608  // 32*64*64*64

__device__ float g_enorm[KCODES];
__device__ float g_loss;

__global__ void vq_prep(const float* __restrict__ emb) {
    int k = blockIdx.x * blockDim.x + threadIdx.x;
    if (k == 0) g_loss = 0.0f;
    if (k < KCODES) {
        const float4* r = reinterpret_cast<const float4*>(emb + k * CDIM);
        float s = 0.0f;
#pragma unroll
        for (int i = 0; i < CDIM / 4; i++) {
            float4 v = r[i];
            s += v.x * v.x + v.y * v.y + v.z * v.z + v.w * v.w;
        }
        g_enorm[k] = s;
    }
}

struct SmemLayout {
    float sxT[PIX_PER_BLK][PAD];   // x transposed: [pixel][c]
    float se[CODE_TILE][PAD];      // e tile row-major: [code][c]
    float red_s[16][PIX_PER_BLK];
    int   red_i[16][PIX_PER_BLK];
    int   bidx[PIX_PER_BLK];
    float wsum[8];
};

__device__ __forceinline__ void ffma2(unsigned long long& d,
                                      unsigned long long a,
                                      unsigned long long b) {
    asm("fma.rn.f32x2 %0, %1, %2, %0;" : "+l"(d) : "l"(a), "l"(b));
}

extern __shared__ char smem_raw[];

__global__ void __launch_bounds__(256) vq_main(const float* __restrict__ x,
                                               const float* __restrict__ emb,
                                               float* __restrict__ out) {
    SmemLayout& s = *reinterpret_cast<SmemLayout*>(smem_raw);
    const int tid = threadIdx.x;
    const int pg = tid & 15;   // pixel group: pixels pg, pg+16, ..., pg+112
    const int cg = tid >> 4;   // code group: codes cg*8 .. cg*8+7 per tile
    const int n0 = blockIdx.x * PIX_PER_BLK;
    const int b = n0 >> 12;          // batch index (4096 pixels per batch image)
    const int rem = n0 & 4095;       // h*64+w offset within image
    const float* xbase = x + (size_t)b * 262144 + rem;

    // --- Load x tile transposed into smem (scalar: coalesced global, 4-way STS) ---
    for (int i = tid; i < CDIM * PIX_PER_BLK; i += 256) {
        int c = i >> 7, px = i & 127;
        s.sxT[px][c] = xbase[c * 4096 + px];
    }

    float best_s[8];
    int best_i[8];
#pragma unroll
    for (int i = 0; i < 8; i++) { best_s[i] = 3.4e38f; best_i[i] = 0; }

    for (int t = 0; t < NTILES; t++) {
        __syncthreads();  // previous tile's reads done before overwrite
        // --- Load 128-code tile (contiguous 32KB from global/L2, row-major copy) ---
        const float4* esrc = reinterpret_cast<const float4*>(emb + t * CODE_TILE * CDIM);
        for (int i = tid; i < CODE_TILE * (CDIM / 4); i += 256) {
            int k = i >> 4, c4 = i & 15;
            *reinterpret_cast<float4*>(&s.se[k][c4 * 4]) = esrc[i];
        }
        __syncthreads();

        // --- 8 pixels x 8 codes register tile, f32x2 packed along C ---
        unsigned long long acc[8][8];
#pragma unroll
        for (int i = 0; i < 8; i++)
#pragma unroll
            for (int j = 0; j < 8; j++) acc[i][j] = 0ULL;

#pragma unroll 8
        for (int c = 0; c < CDIM; c += 4) {
            ulonglong2 xv[8], ev[8];
#pragma unroll
            for (int i = 0; i < 8; i++)
                xv[i] = *reinterpret_cast<const ulonglong2*>(&s.sxT[pg + 16 * i][c]);
#pragma unroll
            for (int j = 0; j < 8; j++)
                ev[j] = *reinterpret_cast<const ulonglong2*>(&s.se[cg * 8 + j][c]);
#pragma unroll
            for (int i = 0; i < 8; i++)
#pragma unroll
                for (int j = 0; j < 8; j++) {
                    ffma2(acc[i][j], xv[i].x, ev[j].x);
                    ffma2(acc[i][j], xv[i].y, ev[j].y);
                }
        }

        // --- Fold into running argmin: score = ||e||^2 - 2*dot (||x||^2 is constant) ---
#pragma unroll
        for (int j = 0; j < 8; j++) {
            int k = t * CODE_TILE + cg * 8 + j;
            float en = g_enorm[k];
#pragma unroll
            for (int i = 0; i < 8; i++) {
                float lo, hi;
                asm("mov.b64 {%0, %1}, %2;" : "=f"(lo), "=f"(hi) : "l"(acc[i][j]));
                float sc = fmaf(-2.0f, lo + hi, en);
                if (sc < best_s[i]) { best_s[i] = sc; best_i[i] = k; }
            }
        }
    }

    // --- Cross-thread reduction over the 16 code groups ---
    __syncthreads();
#pragma unroll
    for (int i = 0; i < 8; i++) {
        s.red_s[cg][pg + 16 * i] = best_s[i];
        s.red_i[cg][pg + 16 * i] = best_i[i];
    }
    __syncthreads();
    if (tid < PIX_PER_BLK) {
        int px = tid;
        float bs = s.red_s[0][px];
        int bi = s.red_i[0][px];
#pragma unroll
        for (int g = 1; g < 16; g++) {
            float v = s.red_s[g][px];
            int id = s.red_i[g][px];
            if (v < bs || (v == bs && id < bi)) { bs = v; bi = id; }
        }
        s.bidx[px] = bi;
        out[1 + QELEMS + n0 + px] = (float)bi;  // indices as float
    }
    __syncthreads();

    // --- Epilogue: gather quantized, write BCHW, accumulate exact loss ---
    {
        int px = tid & 127;
        int ch = tid >> 7;  // two threads per pixel, each handles 32 of 64 channels
        int bi = s.bidx[px];
        const float4* erow = reinterpret_cast<const float4*>(emb + bi * CDIM);
        float* qout = out + 1 + (size_t)b * 262144 + rem + px;
        float lsum = 0.0f;
#pragma unroll
        for (int cc = 0; cc < 8; cc++) {
            int c = ch * 32 + cc * 4;
            float4 e4 = erow[c >> 2];
            float4 x4 = *reinterpret_cast<const float4*>(&s.sxT[px][c]);
            float d0 = e4.x - x4.x, d1 = e4.y - x4.y;
            float d2 = e4.z - x4.z, d3 = e4.w - x4.w;
            lsum += d0 * d0 + d1 * d1 + d2 * d2 + d3 * d3;
            qout[(size_t)(c + 0) * 4096] = e4.x;
            qout[(size_t)(c + 1) * 4096] = e4.y;
            qout[(size_t)(c + 2) * 4096] = e4.z;
            qout[(size_t)(c + 3) * 4096] = e4.w;
        }
#pragma unroll
        for (int o = 16; o > 0; o >>= 1)
            lsum += __shfl_down_sync(0xffffffffu, lsum, o);
        if ((tid & 31) == 0) s.wsum[tid >> 5] = lsum;
        __syncthreads();
        if (tid == 0) {
            float bsum = 0.0f;
#pragma unroll
            for (int w = 0; w < 8; w++) bsum += s.wsum[w];
            atomicAdd(&g_loss, bsum);
        }
    }
}

__global__ void vq_fin(float* __restrict__ out) {
    out[0] = 0.25f * g_loss * (1.0f / (float)QELEMS);
}

extern "C" void kernel_launch(void* const* d_in, const int* in_sizes, int n_in,
                              void* d_out, int out_size) {
    const float* x = (const float*)d_in[0];
    const float* emb = (const float*)d_in[1];
    // Defensive: swap if metadata order is (embedding, x)
    if (n_in >= 2 && in_sizes[0] == KCODES * CDIM && in_sizes[1] == NPIX * CDIM) {
        const float* tmp = x; x = emb; emb = tmp;
    }
    float* out = (float*)d_out;
    (void)out_size;

    cudaFuncSetAttribute(vq_main, cudaFuncAttributeMaxDynamicSharedMemorySize,
                         (int)sizeof(SmemLayout));

    vq_prep<<<(KCODES + 255) / 256, 256>>>(emb);
    vq_main<<<NPIX / PIX_PER_BLK, 256, sizeof(SmemLayout)>>>(x, emb, out);
    vq_fin<<<1, 1>>>(out);
}

// round 6
// speedup vs baseline: 1.1671x; 1.1671x over previous
#include <cuda_runtime.h>
#include <cuda_bf16.h>
#include <cstdint>

#define KCODES 1024
#define CDIM 64
#define NPIX 131072
#define QELEMS 8388608
#define TH_GAP 0.02f
#define BIGF 3.4e38f

// B planes: [code][0:64)=eh, [64:128)=el  (256KB, L2-resident)
__device__ __align__(16) __nv_bfloat16 g_B[KCODES * 128];
__device__ float g_enorm[KCODES];
__device__ float g_loss;

// ---- smem layout (bytes) ----
#define SM_SX 0                 // float [128][68]
#define SM_SA 34816             // bf16 [128][136]  (cols 0-63 xh, 64-127 xl)
#define SM_SB 69632             // bf16 [128][136]  (cols 0-63 eh, 64-127 el)
#define SM_RB1 104448           // float [2][128]
#define SM_RB2 105472           // float [2][128]
#define SM_RI 106496            // int   [2][128]
#define SM_FS 104448            // reuse RB1: float[256]
#define SM_FI 105472            // reuse RB2: int[256]
#define SM_RIDX 107520          // int [128]
#define SM_FLIST 108032         // int [128]
#define SM_FCNT 108544
#define SM_WSUM 108548          // float[8]
#define SM_TOTAL 108608

__device__ __forceinline__ uint32_t smem_u32(const void* p) {
    return (uint32_t)__cvta_generic_to_shared(p);
}
#define LDSM4(r0, r1, r2, r3, a)                                                  \
    asm volatile("ldmatrix.sync.aligned.m8n8.x4.shared.b16 {%0,%1,%2,%3}, [%4];"  \
                 : "=r"(r0), "=r"(r1), "=r"(r2), "=r"(r3) : "r"(a))
#define MMA16816(d, a, b)                                                         \
    asm volatile("mma.sync.aligned.m16n8k16.row.col.f32.bf16.bf16.f32 "           \
                 "{%0,%1,%2,%3}, {%4,%5,%6,%7}, {%8,%9}, {%0,%1,%2,%3};"          \
                 : "+f"((d)[0]), "+f"((d)[1]), "+f"((d)[2]), "+f"((d)[3])         \
                 : "r"((a)[0]), "r"((a)[1]), "r"((a)[2]), "r"((a)[3]),            \
                   "r"((b)[0]), "r"((b)[1]))
#define CPASYNC16(dst, src)                                                       \
    asm volatile("cp.async.cg.shared.global [%0], [%1], 16;" :: "r"(dst), "l"(src) : "memory")

__device__ __forceinline__ uint32_t packbf(__nv_bfloat16 a, __nv_bfloat16 b) {
    return (uint32_t)__bfloat16_as_ushort(a) | ((uint32_t)__bfloat16_as_ushort(b) << 16);
}

// ---------------- prep: split embedding planes, enorm, zero loss ----------------
__global__ void vq_bsplit(const float* __restrict__ emb) {
    int k = blockIdx.x * 256 + threadIdx.x;
    if (k == 0) g_loss = 0.0f;
    if (k < KCODES) {
        float s = 0.0f;
        __nv_bfloat16* br = g_B + k * 128;
#pragma unroll 8
        for (int c = 0; c < CDIM; c += 2) {
            float v0 = emb[k * CDIM + c], v1 = emb[k * CDIM + c + 1];
            s += v0 * v0 + v1 * v1;
            __nv_bfloat16 h0 = __float2bfloat16(v0), h1 = __float2bfloat16(v1);
            __nv_bfloat16 l0 = __float2bfloat16(v0 - __bfloat162float(h0));
            __nv_bfloat16 l1 = __float2bfloat16(v1 - __bfloat162float(h1));
            *(uint32_t*)(br + c) = packbf(h0, h1);
            *(uint32_t*)(br + 64 + c) = packbf(l0, l1);
        }
        g_enorm[k] = s;
    }
}

// ---------------- fused main: split + HMMA argmin + fixup + gather + loss ----------------
extern __shared__ char sm_raw[];

__global__ void __launch_bounds__(256, 2) vq_main(const float* __restrict__ x,
                                                  const float* __restrict__ emb,
                                                  float* __restrict__ out) {
    char* sm = sm_raw;
    float* sx = reinterpret_cast<float*>(sm + SM_SX);
    __nv_bfloat16* sA = reinterpret_cast<__nv_bfloat16*>(sm + SM_SA);
    __nv_bfloat16* sB = reinterpret_cast<__nv_bfloat16*>(sm + SM_SB);
    int* fcnt = reinterpret_cast<int*>(sm + SM_FCNT);

    const int tid = threadIdx.x, l = tid & 31, w = tid >> 5;
    const int wm = w & 3, wn = w >> 2;
    const int n0 = blockIdx.x * 128;
    const int b = n0 >> 12, rem = n0 & 4095;
    const float* xb = x + (size_t)b * 262144 + rem;

    if (tid == 0) *fcnt = 0;
    // load x tile (transposed, coalesced 512B rows)
    for (int i = tid; i < CDIM * 128; i += 256) {
        int c = i >> 7, p = i & 127;
        sx[p * 68 + c] = xb[c * 4096 + p];
    }
    __syncthreads();
    // split x -> sA (xh | xl)
    {
        int p = tid >> 1, hh = tid & 1;
        const float* xr = sx + p * 68 + hh * 32;
        __nv_bfloat16* ar = sA + p * 136 + hh * 32;
#pragma unroll
        for (int c = 0; c < 32; c += 2) {
            float v0 = xr[c], v1 = xr[c + 1];
            __nv_bfloat16 h0 = __float2bfloat16(v0), h1 = __float2bfloat16(v1);
            __nv_bfloat16 l0 = __float2bfloat16(v0 - __bfloat162float(h0));
            __nv_bfloat16 l1 = __float2bfloat16(v1 - __bfloat162float(h1));
            *(uint32_t*)(ar + c) = packbf(h0, h1);
            *(uint32_t*)(ar + 64 + c) = packbf(l0, l1);
        }
    }

    // lane-constant ldmatrix address components
    const uint32_t sAb = smem_u32(sA), sBb = smem_u32(sB);
    const int lr = l & 7;
    const int aRow = wm * 32 + lr + ((l >> 3) & 1) * 8;  // + mt*16
    const int aColS = ((l >> 4) & 1) * 8;                // + ka
    const int bRow = wn * 64 + lr + ((l >> 4) & 1) * 8;  // + q4*16
    const int bColS = ((l >> 3) & 1) * 8;                // + kb

    float B1[4] = {BIGF, BIGF, BIGF, BIGF};
    float B2[4] = {BIGF, BIGF, BIGF, BIGF};
    int I1[4] = {0, 0, 0, 0};

    for (int nt = 0; nt < 8; nt++) {
        __syncthreads();  // previous tile's sB reads done
        {
            const char* bsrc = reinterpret_cast<const char*>(g_B) + (size_t)nt * 128 * 256;
            for (int i = tid; i < 2048; i += 256) {
                int r = i >> 4, q = i & 15;
                CPASYNC16(sBb + r * 272 + q * 16, bsrc + r * 256 + q * 16);
            }
            asm volatile("cp.async.commit_group;\ncp.async.wait_group 0;" ::: "memory");
        }
        __syncthreads();

        float acc[2][8][4];
#pragma unroll
        for (int mt = 0; mt < 2; mt++)
#pragma unroll
            for (int q = 0; q < 8; q++)
#pragma unroll
                for (int cc = 0; cc < 4; cc++) acc[mt][q][cc] = 0.0f;

#pragma unroll
        for (int ks = 0; ks < 12; ks++) {
            const int k = ks * 16;
            const int ka = (k < 128) ? k : (k - 128);       // A: [xh|xl|xh]
            const int kb = (k < 128) ? (k & 63) : (k - 64); // B: [eh|eh|el]
            uint32_t af[2][4];
#pragma unroll
            for (int mt = 0; mt < 2; mt++)
                LDSM4(af[mt][0], af[mt][1], af[mt][2], af[mt][3],
                      sAb + (uint32_t)(aRow + mt * 16) * 272 + (uint32_t)(ka + aColS) * 2);
            uint32_t bf[8][2];
#pragma unroll
            for (int q4 = 0; q4 < 4; q4++) {
                uint32_t r0, r1, r2, r3;
                LDSM4(r0, r1, r2, r3,
                      sBb + (uint32_t)(bRow + q4 * 16) * 272 + (uint32_t)(kb + bColS) * 2);
                bf[q4 * 2][0] = r0; bf[q4 * 2][1] = r1;
                bf[q4 * 2 + 1][0] = r2; bf[q4 * 2 + 1][1] = r3;
            }
#pragma unroll
            for (int mt = 0; mt < 2; mt++)
#pragma unroll
                for (int q = 0; q < 8; q++) MMA16816(acc[mt][q], af[mt], bf[q]);
        }

        // fold scores into running best/second (codes ascend per lane -> simple <)
        const int kwb = nt * 128 + wn * 64 + 2 * (l & 3);
#pragma unroll
        for (int mt = 0; mt < 2; mt++)
#pragma unroll
            for (int q = 0; q < 8; q++)
#pragma unroll
                for (int cc = 0; cc < 4; cc++) {
                    int code = kwb + q * 8 + (cc & 1);
                    int s = mt * 2 + (cc >> 1);
                    float sc = fmaf(-2.0f, acc[mt][q][cc], __ldg(&g_enorm[code]));
                    if (sc < B1[s]) { B2[s] = B1[s]; B1[s] = sc; I1[s] = code; }
                    else B2[s] = fminf(B2[s], sc);
                }
    }

    // quad reduce (lanes 4j..4j+3 share pixels; width=4 shfl)
#pragma unroll
    for (int off = 1; off <= 2; off <<= 1)
#pragma unroll
        for (int s = 0; s < 4; s++) {
            float ob1 = __shfl_down_sync(0xffffffffu, B1[s], off, 4);
            float ob2 = __shfl_down_sync(0xffffffffu, B2[s], off, 4);
            int oi = __shfl_down_sync(0xffffffffu, I1[s], off, 4);
            if (ob1 < B1[s] || (ob1 == B1[s] && oi < I1[s])) {
                B2[s] = fminf(ob2, B1[s]); B1[s] = ob1; I1[s] = oi;
            } else B2[s] = fminf(B2[s], ob1);
        }
    {
        float* rb1 = reinterpret_cast<float*>(sm + SM_RB1);
        float* rb2 = reinterpret_cast<float*>(sm + SM_RB2);
        int* ri = reinterpret_cast<int*>(sm + SM_RI);
        if ((l & 3) == 0) {
#pragma unroll
            for (int s = 0; s < 4; s++) {
                int p = wm * 32 + s * 8 + (l >> 2);
                rb1[wn * 128 + p] = B1[s];
                rb2[wn * 128 + p] = B2[s];
                ri[wn * 128 + p] = I1[s];
            }
        }
    }
    __syncthreads();

    int* ridx = reinterpret_cast<int*>(sm + SM_RIDX);
    int* flist = reinterpret_cast<int*>(sm + SM_FLIST);
    if (tid < 128) {
        float* rb1 = reinterpret_cast<float*>(sm + SM_RB1);
        float* rb2 = reinterpret_cast<float*>(sm + SM_RB2);
        int* ri = reinterpret_cast<int*>(sm + SM_RI);
        float a1 = rb1[tid], a2 = rb2[tid]; int ai = ri[tid];
        float c1 = rb1[128 + tid], c2 = rb2[128 + tid]; int ci = ri[128 + tid];
        float best, second; int bi;
        if (c1 < a1 || (c1 == a1 && ci < ai)) { best = c1; bi = ci; second = fminf(c2, a1); }
        else { best = a1; bi = ai; second = fminf(a2, c1); }
        ridx[tid] = bi;
        if (second - best < TH_GAP) {
            int pos = atomicAdd(fcnt, 1);
            flist[pos] = tid;
        }
    }
    __syncthreads();

    // exact fp32 fixup for close calls (matches R1's proven-exact math)
    {
        float* fs = reinterpret_cast<float*>(sm + SM_FS);
        int* fi = reinterpret_cast<int*>(sm + SM_FI);
        int nf = *fcnt;
        for (int f = 0; f < nf; f++) {
            int px = flist[f];
            float best = BIGF; int bidx = 0;
#pragma unroll
            for (int kk = 0; kk < 4; kk++) {
                int k = tid * 4 + kk;
                const float4* er = reinterpret_cast<const float4*>(emb + k * CDIM);
                float dot = 0.0f;
#pragma unroll
                for (int c4 = 0; c4 < 16; c4++) {
                    float4 e4 = er[c4];
                    float4 x4 = *reinterpret_cast<const float4*>(&sx[px * 68 + c4 * 4]);
                    dot += e4.x * x4.x + e4.y * x4.y + e4.z * x4.z + e4.w * x4.w;
                }
                float sc = fmaf(-2.0f, dot, __ldg(&g_enorm[k]));
                if (sc < best) { best = sc; bidx = k; }
            }
            fs[tid] = best; fi[tid] = bidx;
            __syncthreads();
            if (tid == 0) {
                float bb = fs[0]; int bi2 = fi[0];
                for (int t = 1; t < 256; t++)
                    if (fs[t] < bb || (fs[t] == bb && fi[t] < bi2)) { bb = fs[t]; bi2 = fi[t]; }
                ridx[px] = bi2;
            }
            __syncthreads();
        }
    }

    if (tid < 128) out[1 + QELEMS + n0 + tid] = (float)ridx[tid];

    // gather quantized (exact f32 from emb), write BCHW, accumulate loss
    {
        float* wsum = reinterpret_cast<float*>(sm + SM_WSUM);
        int px = tid & 127, ch = tid >> 7;
        int bi = ridx[px];
        const float4* erow = reinterpret_cast<const float4*>(emb + bi * CDIM);
        float* qout = out + 1 + (size_t)b * 262144 + rem + px;
        float lsum = 0.0f;
#pragma unroll
        for (int cc = 0; cc < 8; cc++) {
            int c = ch * 32 + cc * 4;
            float4 e4 = erow[c >> 2];
            float4 x4 = *reinterpret_cast<const float4*>(&sx[px * 68 + c]);
            float d0 = e4.x - x4.x, d1 = e4.y - x4.y;
            float d2 = e4.z - x4.z, d3 = e4.w - x4.w;
            lsum += d0 * d0 + d1 * d1 + d2 * d2 + d3 * d3;
            qout[(size_t)(c + 0) * 4096] = e4.x;
            qout[(size_t)(c + 1) * 4096] = e4.y;
            qout[(size_t)(c + 2) * 4096] = e4.z;
            qout[(size_t)(c + 3) * 4096] = e4.w;
        }
#pragma unroll
        for (int o = 16; o > 0; o >>= 1) lsum += __shfl_down_sync(0xffffffffu, lsum, o);
        if ((tid & 31) == 0) wsum[tid >> 5] = lsum;
        __syncthreads();
        if (tid == 0) {
            float bsum = 0.0f;
#pragma unroll
            for (int ww = 0; ww < 8; ww++) bsum += wsum[ww];
            atomicAdd(&g_loss, bsum);
        }
    }
}

__global__ void vq_fin(float* __restrict__ out) {
    out[0] = 0.25f * g_loss * (1.0f / (float)QELEMS);
}

extern "C" void kernel_launch(void* const* d_in, const int* in_sizes, int n_in,
                              void* d_out, int out_size) {
    const float* x = (const float*)d_in[0];
    const float* emb = (const float*)d_in[1];
    if (n_in >= 2 && in_sizes[0] == KCODES * CDIM && in_sizes[1] == NPIX * CDIM) {
        const float* t = x; x = emb; emb = t;
    }
    float* out = (float*)d_out;
    (void)out_size;

    cudaFuncSetAttribute(vq_main, cudaFuncAttributeMaxDynamicSharedMemorySize, SM_TOTAL);

    vq_bsplit<<<4, 256>>>(emb);
    vq_main<<<NPIX / 128, 256, SM_TOTAL>>>(x, emb, out);
    vq_fin<<<1, 1>>>(out);
}

// round 7
// speedup vs baseline: 1.7019x; 1.4582x over previous
#include <cuda_runtime.h>
#include <cuda_fp16.h>
#include <cstdint>

#define KCODES 1024
#define CDIM 64
#define NPIX 131072
#define QELEMS 8388608
#define TH2 0.045f      // gap threshold on score/2
#define BIGF 3.4e38f

// g_B: -fp16(e)  [code][64]
__device__ __align__(16) __half g_B[KCODES * CDIM];
__device__ float g_enorm[KCODES];
__device__ float g_loss;

// ---- smem layout (bytes) ----
// loop phase:    sA [128][72]h @0 (18432) | sB0 @18432 | sB1 @36864 | en2 @55296
// epilogue:      sx f32 [128][68] @0 (34816, overlaps sA+sB0)
#define SM_SA 0
#define SM_SB0 18432
#define SM_SB1 36864
#define SM_EN 55296
#define SM_RB1 59392
#define SM_RB2 60416
#define SM_RI 61440
#define SM_RIDX 62464
#define SM_FLIST 62976
#define SM_FCNT 63488
#define SM_WSUM 63492
#define SM_FS 63552
#define SM_FI 64576
#define SM_TOTAL 65600
#define AROWB 144       // 72 halves per row (conflict-free ldmatrix stride)

__device__ __forceinline__ uint32_t smem_u32(const void* p) {
    return (uint32_t)__cvta_generic_to_shared(p);
}
#define LDSM4(r0, r1, r2, r3, a)                                                  \
    asm volatile("ldmatrix.sync.aligned.m8n8.x4.shared.b16 {%0,%1,%2,%3}, [%4];"  \
                 : "=r"(r0), "=r"(r1), "=r"(r2), "=r"(r3) : "r"(a))
#define MMA16816(d, a, b)                                                         \
    asm volatile("mma.sync.aligned.m16n8k16.row.col.f32.f16.f16.f32 "             \
                 "{%0,%1,%2,%3}, {%4,%5,%6,%7}, {%8,%9}, {%0,%1,%2,%3};"          \
                 : "+f"((d)[0]), "+f"((d)[1]), "+f"((d)[2]), "+f"((d)[3])         \
                 : "r"((a)[0]), "r"((a)[1]), "r"((a)[2]), "r"((a)[3]),            \
                   "r"((b)[0]), "r"((b)[1]))
#define CPASYNC16(dst, src)                                                       \
    asm volatile("cp.async.cg.shared.global [%0], [%1], 16;" :: "r"(dst), "l"(src) : "memory")

// ---------------- prep: B = -fp16(e), enorm, zero loss ----------------
__global__ void vq_bsplit(const float* __restrict__ emb) {
    int k = blockIdx.x * 128 + threadIdx.x;
    if (k == 0) g_loss = 0.0f;
    if (k < KCODES) {
        float s = 0.0f;
        __half* br = g_B + k * CDIM;
#pragma unroll 8
        for (int c = 0; c < CDIM; c += 2) {
            float v0 = emb[k * CDIM + c], v1 = emb[k * CDIM + c + 1];
            s += v0 * v0 + v1 * v1;
            __half2 h = __floats2half2_rn(-v0, -v1);
            *reinterpret_cast<__half2*>(br + c) = h;
        }
        g_enorm[k] = s;
    }
}

// ---------------- fused main ----------------
extern __shared__ char sm_raw[];

__global__ void __launch_bounds__(256, 2) vq_main(const float* __restrict__ x,
                                                  const float* __restrict__ emb,
                                                  float* __restrict__ out) {
    char* sm = sm_raw;
    __half* sA = reinterpret_cast<__half*>(sm + SM_SA);
    float* en2 = reinterpret_cast<float*>(sm + SM_EN);
    int* fcnt = reinterpret_cast<int*>(sm + SM_FCNT);

    const int tid = threadIdx.x, l = tid & 31, w = tid >> 5;
    const int wm = w & 3, wn = w >> 2;
    const int n0 = blockIdx.x * 128;
    const int b = n0 >> 12, rem = n0 & 4095;
    const float* xb = x + (size_t)b * 262144 + rem;

    const uint32_t sBb = smem_u32(sm);

    // prologue: start tile 0 load immediately
    {
        const char* bsrc = reinterpret_cast<const char*>(g_B);
        for (int ch = tid; ch < 1024; ch += 256) {
            int r = ch >> 3, q = ch & 7;
            CPASYNC16(sBb + SM_SB0 + r * AROWB + q * 16, bsrc + r * 128 + q * 16);
        }
        asm volatile("cp.async.commit_group;" ::: "memory");
    }

    if (tid == 0) *fcnt = 0;
    for (int i = tid; i < KCODES; i += 256) en2[i] = 0.5f * g_enorm[i];
    // x tile -> fp16 transposed into sA
    for (int i = tid; i < CDIM * 128; i += 256) {
        int c = i >> 7, p = i & 127;
        sA[p * 72 + c] = __float2half(xb[c * 4096 + p]);
    }

    // lane-constant ldmatrix address parts
    const int lr = l & 7;
    const uint32_t aBase = sBb + SM_SA +
        (uint32_t)(wm * 32 + lr + ((l >> 3) & 1) * 8) * AROWB + ((l >> 4) & 1) * 16;
    const uint32_t bOff =
        (uint32_t)(wn * 64 + lr + ((l >> 4) & 1) * 8) * AROWB + ((l >> 3) & 1) * 16;

    float B1[4] = {BIGF, BIGF, BIGF, BIGF};
    float B2[4] = {BIGF, BIGF, BIGF, BIGF};
    int I1[4] = {0, 0, 0, 0};
    const int kwl = wn * 64 + 2 * (l & 3);

    uint32_t bufOff[2] = {SM_SB0, SM_SB1};

    for (int nt = 0; nt < 8; nt++) {
        if (nt < 7) {  // prefetch next tile
            const char* bsrc = reinterpret_cast<const char*>(g_B) + (size_t)(nt + 1) * 16384;
            uint32_t dstb = sBb + bufOff[(nt + 1) & 1];
            for (int ch = tid; ch < 1024; ch += 256) {
                int r = ch >> 3, q = ch & 7;
                CPASYNC16(dstb + r * AROWB + q * 16, bsrc + r * 128 + q * 16);
            }
            asm volatile("cp.async.commit_group;\ncp.async.wait_group 1;" ::: "memory");
        } else {
            asm volatile("cp.async.wait_group 0;" ::: "memory");
        }
        __syncthreads();

        // init acc = enorm/2 (per-code), then acc -= xh.eh via MMA (B = -eh)
        float acc[2][8][4];
#pragma unroll
        for (int q = 0; q < 8; q++)
#pragma unroll
            for (int c1 = 0; c1 < 2; c1++) {
                float e = en2[nt * 128 + kwl + q * 8 + c1];
                acc[0][q][c1] = e; acc[0][q][c1 + 2] = e;
                acc[1][q][c1] = e; acc[1][q][c1 + 2] = e;
            }

        const uint32_t bBase = sBb + bufOff[nt & 1] + bOff;
#pragma unroll
        for (int ks = 0; ks < 4; ks++) {
            uint32_t af[2][4];
#pragma unroll
            for (int mt = 0; mt < 2; mt++)
                LDSM4(af[mt][0], af[mt][1], af[mt][2], af[mt][3],
                      aBase + (uint32_t)mt * 16 * AROWB + (uint32_t)ks * 32);
            uint32_t bf[8][2];
#pragma unroll
            for (int q4 = 0; q4 < 4; q4++) {
                uint32_t r0, r1, r2, r3;
                LDSM4(r0, r1, r2, r3, bBase + (uint32_t)q4 * 16 * AROWB + (uint32_t)ks * 32);
                bf[q4 * 2][0] = r0; bf[q4 * 2][1] = r1;
                bf[q4 * 2 + 1][0] = r2; bf[q4 * 2 + 1][1] = r3;
            }
#pragma unroll
            for (int mt = 0; mt < 2; mt++)
#pragma unroll
                for (int q = 0; q < 8; q++) MMA16816(acc[mt][q], af[mt], bf[q]);
        }

        // fold scores (acc == score/2) into best/second
        const int kwb = nt * 128 + kwl;
#pragma unroll
        for (int mt = 0; mt < 2; mt++)
#pragma unroll
            for (int q = 0; q < 8; q++)
#pragma unroll
                for (int cc = 0; cc < 4; cc++) {
                    int code = kwb + q * 8 + (cc & 1);
                    int s = mt * 2 + (cc >> 1);
                    float sc = acc[mt][q][cc];
                    if (sc < B1[s]) { B2[s] = B1[s]; B1[s] = sc; I1[s] = code; }
                    else B2[s] = fminf(B2[s], sc);
                }
        __syncthreads();  // all reads of buf[nt&1] + sA done for this tile
    }

    // quad reduce (lanes 4j..4j+3 share pixel rows)
#pragma unroll
    for (int off = 1; off <= 2; off <<= 1)
#pragma unroll
        for (int s = 0; s < 4; s++) {
            float ob1 = __shfl_down_sync(0xffffffffu, B1[s], off, 4);
            float ob2 = __shfl_down_sync(0xffffffffu, B2[s], off, 4);
            int oi = __shfl_down_sync(0xffffffffu, I1[s], off, 4);
            if (ob1 < B1[s] || (ob1 == B1[s] && oi < I1[s])) {
                B2[s] = fminf(ob2, B1[s]); B1[s] = ob1; I1[s] = oi;
            } else B2[s] = fminf(B2[s], ob1);
        }
    {
        float* rb1 = reinterpret_cast<float*>(sm + SM_RB1);
        float* rb2 = reinterpret_cast<float*>(sm + SM_RB2);
        int* ri = reinterpret_cast<int*>(sm + SM_RI);
        if ((l & 3) == 0)
#pragma unroll
            for (int s = 0; s < 4; s++) {
                int p = wm * 32 + s * 8 + (l >> 2);
                rb1[wn * 128 + p] = B1[s];
                rb2[wn * 128 + p] = B2[s];
                ri[wn * 128 + p] = I1[s];
            }
    }

    // reload exact fp32 x into sx (overlaps sA/sB0 -- loop is done)
    float* sx = reinterpret_cast<float*>(sm + SM_SA);
    for (int i = tid; i < CDIM * 128; i += 256) {
        int c = i >> 7, p = i & 127;
        sx[p * 68 + c] = xb[c * 4096 + p];
    }
    __syncthreads();

    int* ridx = reinterpret_cast<int*>(sm + SM_RIDX);
    int* flist = reinterpret_cast<int*>(sm + SM_FLIST);
    if (tid < 128) {
        float* rb1 = reinterpret_cast<float*>(sm + SM_RB1);
        float* rb2 = reinterpret_cast<float*>(sm + SM_RB2);
        int* ri = reinterpret_cast<int*>(sm + SM_RI);
        float a1 = rb1[tid], a2 = rb2[tid]; int ai = ri[tid];
        float c1 = rb1[128 + tid], c2 = rb2[128 + tid]; int ci = ri[128 + tid];
        float best, second; int bi;
        if (c1 < a1 || (c1 == a1 && ci < ai)) { best = c1; bi = ci; second = fminf(c2, a1); }
        else { best = a1; bi = ai; second = fminf(a2, c1); }
        ridx[tid] = bi;
        if (second - best < TH2) {
            int pos = atomicAdd(fcnt, 1);
            flist[pos] = tid;
        }
    }
    __syncthreads();

    // exact fp32 fixup for close calls (reference-grade argmin)
    {
        float* fs = reinterpret_cast<float*>(sm + SM_FS);
        int* fi = reinterpret_cast<int*>(sm + SM_FI);
        int nf = *fcnt;
        for (int f = 0; f < nf; f++) {
            int px = flist[f];
            float best = BIGF; int bidx = 0;
#pragma unroll
            for (int kk = 0; kk < 4; kk++) {
                int k = tid * 4 + kk;
                const float4* er = reinterpret_cast<const float4*>(emb + k * CDIM);
                float dot = 0.0f;
#pragma unroll
                for (int c4 = 0; c4 < 16; c4++) {
                    float4 e4 = er[c4];
                    float4 x4 = *reinterpret_cast<const float4*>(&sx[px * 68 + c4 * 4]);
                    dot += e4.x * x4.x + e4.y * x4.y + e4.z * x4.z + e4.w * x4.w;
                }
                float sc = fmaf(-2.0f, dot, __ldg(&g_enorm[k]));
                if (sc < best) { best = sc; bidx = k; }
            }
#pragma unroll
            for (int off = 16; off > 0; off >>= 1) {
                float os = __shfl_down_sync(0xffffffffu, best, off);
                int oi = __shfl_down_sync(0xffffffffu, bidx, off);
                if (os < best || (os == best && oi < bidx)) { best = os; bidx = oi; }
            }
            if (l == 0) { fs[w] = best; fi[w] = bidx; }
            __syncthreads();
            if (tid == 0) {
                float bb = fs[0]; int bi2 = fi[0];
#pragma unroll
                for (int t = 1; t < 8; t++)
                    if (fs[t] < bb || (fs[t] == bb && fi[t] < bi2)) { bb = fs[t]; bi2 = fi[t]; }
                ridx[px] = bi2;
            }
            __syncthreads();
        }
    }

    if (tid < 128) out[1 + QELEMS + n0 + tid] = (float)ridx[tid];

    // gather quantized (exact f32), write BCHW, accumulate loss
    {
        float* wsum = reinterpret_cast<float*>(sm + SM_WSUM);
        int px = tid & 127, ch = tid >> 7;
        int bi = ridx[px];
        const float4* erow = reinterpret_cast<const float4*>(emb + bi * CDIM);
        float* qout = out + 1 + (size_t)b * 262144 + rem + px;
        float lsum = 0.0f;
#pragma unroll
        for (int cc = 0; cc < 8; cc++) {
            int c = ch * 32 + cc * 4;
            float4 e4 = erow[c >> 2];
            float4 x4 = *reinterpret_cast<const float4*>(&sx[px * 68 + c]);
            float d0 = e4.x - x4.x, d1 = e4.y - x4.y;
            float d2 = e4.z - x4.z, d3 = e4.w - x4.w;
            lsum += d0 * d0 + d1 * d1 + d2 * d2 + d3 * d3;
            qout[(size_t)(c + 0) * 4096] = e4.x;
            qout[(size_t)(c + 1) * 4096] = e4.y;
            qout[(size_t)(c + 2) * 4096] = e4.z;
            qout[(size_t)(c + 3) * 4096] = e4.w;
        }
#pragma unroll
        for (int o = 16; o > 0; o >>= 1) lsum += __shfl_down_sync(0xffffffffu, lsum, o);
        if ((tid & 31) == 0) wsum[tid >> 5] = lsum;
        __syncthreads();
        if (tid == 0) {
            float bsum = 0.0f;
#pragma unroll
            for (int ww = 0; ww < 8; ww++) bsum += wsum[ww];
            atomicAdd(&g_loss, bsum);
        }
    }
}

__global__ void vq_fin(float* __restrict__ out) {
    out[0] = 0.25f * g_loss * (1.0f / (float)QELEMS);
}

extern "C" void kernel_launch(void* const* d_in, const int* in_sizes, int n_in,
                              void* d_out, int out_size) {
    const float* x = (const float*)d_in[0];
    const float* emb = (const float*)d_in[1];
    if (n_in >= 2 && in_sizes[0] == KCODES * CDIM && in_sizes[1] == NPIX * CDIM) {
        const float* t = x; x = emb; emb = t;
    }
    float* out = (float*)d_out;
    (void)out_size;

    cudaFuncSetAttribute(vq_main, cudaFuncAttributeMaxDynamicSharedMemorySize, SM_TOTAL);

    vq_bsplit<<<8, 128>>>(emb);
    vq_main<<<NPIX / 128, 256, SM_TOTAL>>>(x, emb, out);
    vq_fin<<<1, 1>>>(out);
}